// round 14
// baseline (speedup 1.0000x reference)
#include <cuda_runtime.h>
#include <math.h>

// Dims
#define Bx 16
#define Tx 64
#define Sx 32
#define Fx 128
#define Hx 128
#define NHx 4
#define HS 4096      // H*S
#define ROW 262144   // T*S*F
#define T63OFF 258048 // 63*S*F

// Output layout (flattened tuple concat): x_hat1 | z1 | z2 | KL1 | KL2
#define OFF_Z1 4194304
#define OFF_Z2 4196352
#define OFF_KL1 4198400
#define OFF_KL2 4198401

#define GSLICES 128                         // k-slices per gate in k_gates2 (32 rows each)
// smem: hid,q,k,v each [128][33] floats + wq/wk/wv [3][32][128]
#define ENC_SMEM ((4 * 128 * 33 + 3 * 4096) * 4)

// float4 column split for k_dec3: t63 slice = [64512, 65536), rest = [0, 64512)
#define J4_T63 64512
#define J4_ALL 65536
#define T63_J4N 1024        // float4 columns in the t63 slice
#define T63_KC 16           // k-chunks (8 k each) in stage A

// ---------------- scratch (device globals; no allocation allowed) ----------------
__device__ float g_att[Bx * NHx * Hx * Sx];
__device__ float g_gpart[3 * GSLICES * Bx * Hx];   // 3MB partials
__device__ float g_h2[Bx * Hx];
__device__ double g_klpart1[Bx];
__device__ double g_klpart2[Bx];
__device__ float4 g_p63[T63_KC * Bx * T63_J4N];    // 4MB partials for t63 slice

// ---------------- JAX threefry2x32 (partitionable) -> normal ----------------
__device__ __forceinline__ float tf_normal(unsigned int key1, unsigned int i) {
    unsigned int x0 = 0u, x1 = i;
    unsigned int ks0 = 0u, ks1 = key1, ks2 = key1 ^ 0x1BD11BDAu;
    x0 += ks0; x1 += ks1;
#define TFR(r) { x0 += x1; x1 = (x1 << (r)) | (x1 >> (32 - (r))); x1 ^= x0; }
    TFR(13) TFR(15) TFR(26) TFR(6)
    x0 += ks1; x1 += ks2 + 1u;
    TFR(17) TFR(29) TFR(16) TFR(24)
    x0 += ks2; x1 += ks0 + 2u;
    TFR(13) TFR(15) TFR(26) TFR(6)
    x0 += ks0; x1 += ks1 + 3u;
    TFR(17) TFR(29) TFR(16) TFR(24)
    x0 += ks1; x1 += ks2 + 4u;
    TFR(13) TFR(15) TFR(26) TFR(6)
    x0 += ks2; x1 += ks0 + 5u;
#undef TFR
    unsigned int bits = x0 ^ x1;
    float f = __uint_as_float((bits >> 9) | 0x3F800000u) - 1.0f;
    const float lo = -0.99999994f;
    float u = f * 2.0f + lo;
    u = fmaxf(u, lo);
    return 1.4142135623730951f * erfinvf(u);
}

// ---------------- fused encode: hid + qkv + single-pass attention per (b, head) ----------------
__global__ void __launch_bounds__(384)
k_enc(const float* __restrict__ src,   // x (or xhat) + 63*S*F; stride ROW per b
      const float* __restrict__ w_enc, const float* __restrict__ b_enc,
      const float* __restrict__ wq, const float* __restrict__ bq,
      const float* __restrict__ wk, const float* __restrict__ bk,
      const float* __restrict__ wv, const float* __restrict__ bv) {
    extern __shared__ float sm[];
    float* hid = sm;                     // [128][33]
    float* qs  = sm + 128 * 33;
    float* ks  = sm + 2 * 128 * 33;
    float* vs  = sm + 3 * 128 * 33;
    float* wsm = sm + 4 * 128 * 33;      // [3][32][128] = wq|wk|wv
    int xid = blockIdx.x;                // b*4 + n
    int b = xid >> 2, n = xid & 3;
    int tid = threadIdx.x;
    const float* xb = src + (size_t)b * ROW;

    // Stage qkv weight matrices into smem (overlaps with phase-1 gmem work)
    for (int i = tid; i < 3 * 4096; i += 384) {
        const float* W = (i < 4096) ? wq : (i < 8192 ? wk : wv);
        wsm[i] = W[i & 4095];
    }

    // Phase 1: hid[h][s] = b_enc[h] + sum_f x[s,f] * w_enc[f,h]  (2-way s ILP per thread)
    {
        int h = tid & 127;
        int grp = tid >> 7;              // 0..2
        int s0 = (grp == 0) ? 0 : (grp == 1 ? 11 : 22);
        int s1 = (grp == 0) ? 11 : (grp == 1 ? 22 : 32);
        float be = b_enc[h];
        int s = s0;
        for (; s + 2 <= s1; s += 2) {
            float a0 = be, a1 = be;
            const float* x0 = xb + s * Fx;
            const float* x1 = xb + (s + 1) * Fx;
            #pragma unroll 8
            for (int f = 0; f < Fx; ++f) {
                float w = w_enc[f * Hx + h];
                a0 = fmaf(x0[f], w, a0);
                a1 = fmaf(x1[f], w, a1);
            }
            hid[h * 33 + s] = a0;
            hid[h * 33 + s + 1] = a1;
        }
        if (s < s1) {
            float a0 = be;
            const float* x0 = xb + s * Fx;
            #pragma unroll 8
            for (int f = 0; f < Fx; ++f)
                a0 = fmaf(x0[f], w_enc[f * Hx + h], a0);
            hid[h * 33 + s] = a0;
        }
    }
    __syncthreads();

    // Phase 2: q/k/v[h][s] = bias + sum_sp hid[h][sp]*W[sp][n*32+s]
    {
        int m = tid >> 7;                // 0=q 1=k 2=v
        int h = tid & 127;
        const float* Wm   = wsm + m * 4096;
        const float* bias = (m == 0) ? bq : (m == 1) ? bk : bv;
        float* dst        = (m == 0) ? qs : (m == 1) ? ks : vs;
        const float scale = (m == 0) ? 0.08838834764831845f : 1.0f;
        float hreg[32];
        #pragma unroll
        for (int sp = 0; sp < 32; ++sp) hreg[sp] = hid[h * 33 + sp];
        for (int s = 0; s < Sx; s += 4) {
            float4 acc = *(const float4*)&bias[n * Sx + s];
            #pragma unroll
            for (int sp = 0; sp < 32; ++sp) {
                float4 w = *(const float4*)&Wm[sp * 128 + n * Sx + s];
                float hv = hreg[sp];
                acc.x = fmaf(hv, w.x, acc.x);
                acc.y = fmaf(hv, w.y, acc.y);
                acc.z = fmaf(hv, w.z, acc.z);
                acc.w = fmaf(hv, w.w, acc.w);
            }
            dst[h * 33 + s]     = acc.x * scale;
            dst[h * 33 + s + 1] = acc.y * scale;
            dst[h * 33 + s + 2] = acc.z * scale;
            dst[h * 33 + s + 3] = acc.w * scale;
        }
    }
    __syncthreads();

    // Phase 3: single-pass attention (scores O(0.5); safe without max-subtraction).
    if (tid < 256) {
        int h = tid >> 1;
        int half = tid & 1;
        int off = half * 16;
        float qreg[16];
        #pragma unroll
        for (int s = 0; s < 16; ++s) qreg[s] = qs[h * 33 + off + s];

        float l = 0.f;
        float hacc[16];
        #pragma unroll
        for (int s = 0; s < 16; ++s) hacc[s] = 0.f;
        for (int g = 0; g < Hx; g += 2) {
            float sc0 = 0.f, sc1 = 0.f;
            #pragma unroll
            for (int s = 0; s < 16; ++s) {
                sc0 = fmaf(qreg[s], ks[g * 33 + off + s], sc0);
                sc1 = fmaf(qreg[s], ks[(g + 1) * 33 + off + s], sc1);
            }
            sc0 += __shfl_xor_sync(0xffffffffu, sc0, 1);
            sc1 += __shfl_xor_sync(0xffffffffu, sc1, 1);
            float p0 = __expf(sc0);
            float p1 = __expf(sc1);
            l += p0 + p1;
            #pragma unroll
            for (int s = 0; s < 16; ++s) {
                hacc[s] = fmaf(p0, vs[g * 33 + off + s], hacc[s]);
                hacc[s] = fmaf(p1, vs[(g + 1) * 33 + off + s], hacc[s]);
            }
        }
        float inv = 1.0f / l;
        #pragma unroll
        for (int s = 0; s < 16; ++s)
            g_att[(size_t)xid * HS + h * Sx + off + s] = hacc[s] * inv;
    }
}

// ---------------- fused head-mean+relu + gate partial GEMMs ----------------
__global__ void k_gates2(const float* __restrict__ Wi, const float* __restrict__ Wg,
                         const float* __restrict__ Wo) {
    int gate = blockIdx.x >> 7;          // 0..2
    int ksl  = blockIdx.x & 127;         // 0..127
    int k0 = ksl * 32;
    int j = threadIdx.x;
    __shared__ float a_sm[Bx * 32];
    for (int idx = threadIdx.x; idx < Bx * 32; idx += 128) {
        int b = idx >> 5, rr = idx & 31;
        float v = g_att[(size_t)(b * 4 + 0) * HS + k0 + rr]
                + g_att[(size_t)(b * 4 + 1) * HS + k0 + rr]
                + g_att[(size_t)(b * 4 + 2) * HS + k0 + rr]
                + g_att[(size_t)(b * 4 + 3) * HS + k0 + rr];
        a_sm[idx] = fmaxf(0.25f * v, 0.f);
    }
    __syncthreads();
    const float* W = (gate == 0) ? Wi : (gate == 1) ? Wg : Wo;
    float acc[16];
    #pragma unroll
    for (int b = 0; b < 16; ++b) acc[b] = 0.f;
    #pragma unroll 8
    for (int rr = 0; rr < 32; ++rr) {
        float w = W[(size_t)(k0 + rr) * 128 + j];
        #pragma unroll
        for (int b = 0; b < 16; ++b)
            acc[b] = fmaf(a_sm[b * 32 + rr], w, acc[b]);
    }
    #pragma unroll
    for (int b = 0; b < 16; ++b)
        g_gpart[(size_t)blockIdx.x * (Bx * Hx) + b * 128 + j] = acc[b];
}

// ---------------- gate nonlins + h + fc + reparam z + KL partial (+ optional dec12) ----------------
__global__ void k_finz(const float* __restrict__ w_fc, const float* __restrict__ b_fc,
                       float* __restrict__ z_out, unsigned int key1,
                       const float* __restrict__ w1, const float* __restrict__ b1,
                       const float* __restrict__ w2, const float* __restrict__ b2,
                       double* __restrict__ klpart, int do_decode) {
    int b = blockIdx.x;
    int j = threadIdx.x;
    __shared__ float hv[128];
    __shared__ double dred[128];
    float si = 0.f, sg = 0.f, so = 0.f;
    #pragma unroll 16
    for (int p = 0; p < GSLICES; ++p) {
        si += g_gpart[(size_t)(0 * GSLICES + p) * 2048 + b * 128 + j];
        sg += g_gpart[(size_t)(1 * GSLICES + p) * 2048 + b * 128 + j];
        so += g_gpart[(size_t)(2 * GSLICES + p) * 2048 + b * 128 + j];
    }
    float iv = 1.f / (1.f + expf(-si));
    float gv = tanhf(sg);
    float ov = 1.f / (1.f + expf(-so));
    hv[j] = ov * tanhf(iv * gv);         // c = i*g since c0 = 0
    __syncthreads();
    float mu = b_fc[j], lv = b_fc[128 + j];
    #pragma unroll 8
    for (int k = 0; k < 128; ++k) {
        float hh = hv[k];
        mu = fmaf(hh, w_fc[k * 256 + j], mu);
        lv = fmaf(hh, w_fc[k * 256 + 128 + j], lv);
    }
    {
        double md = (double)mu, ld = (double)lv;
        dred[j] = md * md + (expm1(ld) - ld);
    }
    float eps = tf_normal(key1, (unsigned)(b * 128 + j));
    float z = mu + eps * expf(0.5f * lv);
    z_out[b * 128 + j] = z;
    __syncthreads();
    for (int k = 64; k > 0; k >>= 1) {
        if (j < k) dred[j] += dred[j + k];
        __syncthreads();
    }
    if (j == 0) klpart[b] = dred[0];

    if (do_decode) {
        __shared__ float zsm[128], h1[128];
        zsm[j] = z;
        __syncthreads();
        float acc = b1[j];
        #pragma unroll 8
        for (int k = 0; k < 128; ++k) acc = fmaf(zsm[k], w1[k * 128 + j], acc);
        h1[j] = fmaxf(acc, 0.f);
        __syncthreads();
        acc = b2[j];
        #pragma unroll 8
        for (int k = 0; k < 128; ++k) acc = fmaf(h1[k], w2[k * 128 + j], acc);
        g_h2[b * 128 + j] = fmaxf(acc, 0.f);
    }
}

// ---------------- both KL finals ----------------
__global__ void k_klboth(float* __restrict__ kl1, float* __restrict__ kl2) {
    int t = threadIdx.x;
    if (t == 0) {
        double s = 0.0;
        #pragma unroll
        for (int b = 0; b < Bx; ++b) s += g_klpart1[b];
        kl1[0] = (float)(0.5 * s / 2048.0);
    } else if (t == 1) {
        double s = 0.0;
        #pragma unroll
        for (int b = 0; b < Bx; ++b) s += g_klpart2[b];
        kl2[0] = (float)(0.5 * s / 2048.0);
    }
}

// ---------------- t63 slice stage A: partial GEMM over 8-k chunks ----------------
__global__ void __launch_bounds__(128)
k_d63a(const float* __restrict__ w3) {
    int colblk = blockIdx.x >> 4;        // 0..7
    int kc     = blockIdx.x & 15;        // 0..15
    int k0 = kc * 8;
    int tid = threadIdx.x;
    __shared__ float h2s[Bx][8];
    {
        int b = tid >> 3, kk = tid & 7;
        h2s[b][kk] = g_h2[b * 128 + k0 + kk];
    }
    __syncthreads();
    int cj = colblk * 128 + tid;         // 0..1023
    int j4 = J4_T63 + cj;
    const float4* w4 = (const float4*)w3;
    float4 acc[16];
    #pragma unroll
    for (int b = 0; b < 16; ++b) acc[b] = make_float4(0.f, 0.f, 0.f, 0.f);
    #pragma unroll
    for (int kk = 0; kk < 8; ++kk) {
        float4 w = w4[(size_t)(k0 + kk) * J4_ALL + j4];
        #pragma unroll
        for (int b = 0; b < 16; ++b) {
            float hb = h2s[b][kk];
            acc[b].x = fmaf(hb, w.x, acc[b].x);
            acc[b].y = fmaf(hb, w.y, acc[b].y);
            acc[b].z = fmaf(hb, w.z, acc[b].z);
            acc[b].w = fmaf(hb, w.w, acc[b].w);
        }
    }
    #pragma unroll
    for (int b = 0; b < 16; ++b)
        g_p63[((size_t)kc * Bx + b) * T63_J4N + cj] = acc[b];
}

// ---------------- t63 slice stage B: reduce 16 partials + bias -> xhat ----------------
__global__ void __launch_bounds__(128)
k_d63b(const float* __restrict__ b3, float* __restrict__ xhat) {
    int idx = blockIdx.x * 128 + threadIdx.x;   // 0..16383
    int b  = idx >> 10;
    int cj = idx & 1023;
    int j4 = J4_T63 + cj;
    float4 bias = ((const float4*)b3)[j4];
    float4 s = bias;
    #pragma unroll
    for (int kc = 0; kc < T63_KC; ++kc) {
        float4 p = g_p63[((size_t)kc * Bx + b) * T63_J4N + cj];
        s.x += p.x; s.y += p.y; s.z += p.z; s.w += p.w;
    }
    ((float4*)xhat)[(size_t)b * J4_ALL + j4] = s;
}

// ---------------- decoder big GEMM (rest columns), b split into quarters ----------------
// grid 2016 = colblk(504)*4 + bq; 128 threads; 4 float4 accumulators per thread.
// w3 streamed once from DRAM; 3 re-reads hit L2 (w3 ~fits in 126MB L2).
__global__ void __launch_bounds__(128)
k_dec3(const float* __restrict__ w3, const float* __restrict__ b3,
       float* __restrict__ xhat) {
    int bq     = blockIdx.x & 3;         // 0..3: b in [bq*4, bq*4+4)
    int colblk = blockIdx.x >> 2;        // 0..503
    __shared__ float hsm[4 * 128];
    for (int i = threadIdx.x; i < 4 * 128; i += 128)
        hsm[i] = g_h2[bq * 4 * 128 + i];
    __syncthreads();
    int j4 = colblk * 128 + threadIdx.x;
    const float4* w4 = (const float4*)w3;
    float4 bias = ((const float4*)b3)[j4];
    float4 acc[4];
    #pragma unroll
    for (int b = 0; b < 4; ++b) acc[b] = bias;
    #pragma unroll 8
    for (int k = 0; k < 128; ++k) {
        float4 w = w4[(size_t)k * J4_ALL + j4];
        #pragma unroll
        for (int b = 0; b < 4; ++b) {
            float hb = hsm[b * 128 + k];
            acc[b].x = fmaf(hb, w.x, acc[b].x);
            acc[b].y = fmaf(hb, w.y, acc[b].y);
            acc[b].z = fmaf(hb, w.z, acc[b].z);
            acc[b].w = fmaf(hb, w.w, acc[b].w);
        }
    }
    float4* out4 = (float4*)xhat;
    #pragma unroll
    for (int b = 0; b < 4; ++b)
        out4[(size_t)(bq * 4 + b) * J4_ALL + j4] = acc[b];
}

// ---------------- launch ----------------
extern "C" void kernel_launch(void* const* d_in, const int* in_sizes, int n_in,
                              void* d_out, int out_size) {
    const float* x     = (const float*)d_in[0];
    const float* w_enc = (const float*)d_in[1];
    const float* b_enc = (const float*)d_in[2];
    const float* wq = (const float*)d_in[3];
    const float* bq = (const float*)d_in[4];
    const float* wk = (const float*)d_in[5];
    const float* bk = (const float*)d_in[6];
    const float* wv = (const float*)d_in[7];
    const float* bv = (const float*)d_in[8];
    const float* W_ii = (const float*)d_in[9];
    const float* W_ig = (const float*)d_in[13];
    const float* W_io = (const float*)d_in[15];
    const float* w_fc = (const float*)d_in[17];
    const float* b_fc = (const float*)d_in[18];
    const float* w_d1 = (const float*)d_in[19];
    const float* b_d1 = (const float*)d_in[20];
    const float* w_d2 = (const float*)d_in[21];
    const float* b_d2 = (const float*)d_in[22];
    const float* w_d3 = (const float*)d_in[23];
    const float* b_d3 = (const float*)d_in[24];

    float* out  = (float*)d_out;
    float* xhat = out;
    float* z1   = out + OFF_Z1;
    float* z2   = out + OFF_Z2;
    float* kl1  = out + OFF_KL1;
    float* kl2  = out + OFF_KL2;

    static cudaStream_t s_aux = nullptr;
    static cudaEvent_t ev_fork = nullptr, ev_join = nullptr;
    static bool smem_set = false;
    if (s_aux == nullptr) {
        cudaStreamCreateWithFlags(&s_aux, cudaStreamNonBlocking);
        cudaEventCreateWithFlags(&ev_fork, cudaEventDisableTiming);
        cudaEventCreateWithFlags(&ev_join, cudaEventDisableTiming);
    }
    if (!smem_set) {
        cudaFuncSetAttribute(k_enc, cudaFuncAttributeMaxDynamicSharedMemorySize, ENC_SMEM);
        smem_set = true;
    }

    double* klp1;  cudaGetSymbolAddress((void**)&klp1, g_klpart1);
    double* klp2;  cudaGetSymbolAddress((void**)&klp2, g_klpart2);

    // ---- encode 1 (only t = T-1 matters) ----
    k_enc<<<64, 384, ENC_SMEM>>>(x + T63OFF, w_enc, b_enc, wq, bq, wk, bk, wv, bv);
    k_gates2<<<384, 128>>>(W_ii, W_ig, W_io);
    k_finz<<<16, 128>>>(w_fc, b_fc, z1, 1u, w_d1, b_d1, w_d2, b_d2, klp1, 1);

    // fork right after finz: dec3_rest runs concurrently with the t63 slice + encode 2
    cudaEventRecord(ev_fork, 0);
    cudaStreamWaitEvent(s_aux, ev_fork, 0);
    k_dec3<<<2016, 128, 0, s_aux>>>(w_d3, b_d3, xhat);
    cudaEventRecord(ev_join, s_aux);

    // ---- t63 slice (parallel two-stage), unblocks encode 2 fast ----
    k_d63a<<<128, 128>>>(w_d3);
    k_d63b<<<128, 128>>>(b_d3, xhat);

    // ---- encode 2 on x_hat[t=63] (hidden under dec3_rest) ----
    k_enc<<<64, 384, ENC_SMEM>>>(xhat + T63OFF, w_enc, b_enc, wq, bq, wk, bk, wv, bv);
    k_gates2<<<384, 128>>>(W_ii, W_ig, W_io);
    k_finz<<<16, 128>>>(w_fc, b_fc, z2, 2u, w_d1, b_d1, w_d2, b_d2, klp2, 0);
    k_klboth<<<1, 32>>>(kl1, kl2);

    // join
    cudaStreamWaitEvent(0, ev_join, 0);
}

// round 15
// speedup vs baseline: 1.3350x; 1.3350x over previous
#include <cuda_runtime.h>
#include <math.h>

// Dims
#define Bx 16
#define Tx 64
#define Sx 32
#define Fx 128
#define Hx 128
#define NHx 4
#define HS 4096      // H*S
#define ROW 262144   // T*S*F
#define T63OFF 258048 // 63*S*F

// Output layout (flattened tuple concat): x_hat1 | z1 | z2 | KL1 | KL2
#define OFF_Z1 4194304
#define OFF_Z2 4196352
#define OFF_KL1 4198400
#define OFF_KL2 4198401

#define GSLICES 128                         // k-slices per gate in k_gates2 (32 rows each)
// smem: hid,q,k,v each [128][33] floats + wq/wk/wv [3][32][128]
#define ENC_SMEM ((4 * 128 * 33 + 3 * 4096) * 4)

// float4 column split for k_dec3: t63 slice = [64512, 65536), rest = [0, 64512)
#define J4_T63 64512
#define J4_ALL 65536
#define T63_J4N 1024        // float4 columns in the t63 slice
#define T63_KC 16           // k-chunks (8 k each) in stage A

// ---------------- scratch (device globals; no allocation allowed) ----------------
__device__ float g_att[Bx * NHx * Hx * Sx];
__device__ float g_gpart[3 * GSLICES * Bx * Hx];   // 3MB partials
__device__ float g_h2[Bx * Hx];
__device__ double g_klpart1[Bx];
__device__ double g_klpart2[Bx];
__device__ float4 g_p63[T63_KC * Bx * T63_J4N];    // 4MB partials for t63 slice

// ---------------- JAX threefry2x32 (partitionable) -> normal ----------------
__device__ __forceinline__ float tf_normal(unsigned int key1, unsigned int i) {
    unsigned int x0 = 0u, x1 = i;
    unsigned int ks0 = 0u, ks1 = key1, ks2 = key1 ^ 0x1BD11BDAu;
    x0 += ks0; x1 += ks1;
#define TFR(r) { x0 += x1; x1 = (x1 << (r)) | (x1 >> (32 - (r))); x1 ^= x0; }
    TFR(13) TFR(15) TFR(26) TFR(6)
    x0 += ks1; x1 += ks2 + 1u;
    TFR(17) TFR(29) TFR(16) TFR(24)
    x0 += ks2; x1 += ks0 + 2u;
    TFR(13) TFR(15) TFR(26) TFR(6)
    x0 += ks0; x1 += ks1 + 3u;
    TFR(17) TFR(29) TFR(16) TFR(24)
    x0 += ks1; x1 += ks2 + 4u;
    TFR(13) TFR(15) TFR(26) TFR(6)
    x0 += ks2; x1 += ks0 + 5u;
#undef TFR
    unsigned int bits = x0 ^ x1;
    float f = __uint_as_float((bits >> 9) | 0x3F800000u) - 1.0f;
    const float lo = -0.99999994f;
    float u = f * 2.0f + lo;
    u = fmaxf(u, lo);
    return 1.4142135623730951f * erfinvf(u);
}

// ---------------- fused encode: hid + qkv + single-pass attention per (b, head) ----------------
__global__ void __launch_bounds__(384)
k_enc(const float* __restrict__ src,   // x (or xhat) + 63*S*F; stride ROW per b
      const float* __restrict__ w_enc, const float* __restrict__ b_enc,
      const float* __restrict__ wq, const float* __restrict__ bq,
      const float* __restrict__ wk, const float* __restrict__ bk,
      const float* __restrict__ wv, const float* __restrict__ bv) {
    extern __shared__ float sm[];
    float* hid = sm;                     // [128][33]
    float* qs  = sm + 128 * 33;
    float* ks  = sm + 2 * 128 * 33;
    float* vs  = sm + 3 * 128 * 33;
    float* wsm = sm + 4 * 128 * 33;      // [3][32][128] = wq|wk|wv
    int xid = blockIdx.x;                // b*4 + n
    int b = xid >> 2, n = xid & 3;
    int tid = threadIdx.x;
    const float* xb = src + (size_t)b * ROW;

    // Stage qkv weight matrices into smem (overlaps with phase-1 gmem work)
    for (int i = tid; i < 3 * 4096; i += 384) {
        const float* W = (i < 4096) ? wq : (i < 8192 ? wk : wv);
        wsm[i] = W[i & 4095];
    }

    // Phase 1: hid[h][s] = b_enc[h] + sum_f x[s,f] * w_enc[f,h]  (2-way s ILP per thread)
    {
        int h = tid & 127;
        int grp = tid >> 7;              // 0..2
        int s0 = (grp == 0) ? 0 : (grp == 1 ? 11 : 22);
        int s1 = (grp == 0) ? 11 : (grp == 1 ? 22 : 32);
        float be = b_enc[h];
        int s = s0;
        for (; s + 2 <= s1; s += 2) {
            float a0 = be, a1 = be;
            const float* x0 = xb + s * Fx;
            const float* x1 = xb + (s + 1) * Fx;
            #pragma unroll 8
            for (int f = 0; f < Fx; ++f) {
                float w = w_enc[f * Hx + h];
                a0 = fmaf(x0[f], w, a0);
                a1 = fmaf(x1[f], w, a1);
            }
            hid[h * 33 + s] = a0;
            hid[h * 33 + s + 1] = a1;
        }
        if (s < s1) {
            float a0 = be;
            const float* x0 = xb + s * Fx;
            #pragma unroll 8
            for (int f = 0; f < Fx; ++f)
                a0 = fmaf(x0[f], w_enc[f * Hx + h], a0);
            hid[h * 33 + s] = a0;
        }
    }
    __syncthreads();

    // Phase 2: q/k/v[h][s] = bias + sum_sp hid[h][sp]*W[sp][n*32+s]
    {
        int m = tid >> 7;                // 0=q 1=k 2=v
        int h = tid & 127;
        const float* Wm   = wsm + m * 4096;
        const float* bias = (m == 0) ? bq : (m == 1) ? bk : bv;
        float* dst        = (m == 0) ? qs : (m == 1) ? ks : vs;
        const float scale = (m == 0) ? 0.08838834764831845f : 1.0f;
        float hreg[32];
        #pragma unroll
        for (int sp = 0; sp < 32; ++sp) hreg[sp] = hid[h * 33 + sp];
        for (int s = 0; s < Sx; s += 4) {
            float4 acc = *(const float4*)&bias[n * Sx + s];
            #pragma unroll
            for (int sp = 0; sp < 32; ++sp) {
                float4 w = *(const float4*)&Wm[sp * 128 + n * Sx + s];
                float hv = hreg[sp];
                acc.x = fmaf(hv, w.x, acc.x);
                acc.y = fmaf(hv, w.y, acc.y);
                acc.z = fmaf(hv, w.z, acc.z);
                acc.w = fmaf(hv, w.w, acc.w);
            }
            dst[h * 33 + s]     = acc.x * scale;
            dst[h * 33 + s + 1] = acc.y * scale;
            dst[h * 33 + s + 2] = acc.z * scale;
            dst[h * 33 + s + 3] = acc.w * scale;
        }
    }
    __syncthreads();

    // Phase 3: single-pass attention (scores O(0.5); safe without max-subtraction).
    if (tid < 256) {
        int h = tid >> 1;
        int half = tid & 1;
        int off = half * 16;
        float qreg[16];
        #pragma unroll
        for (int s = 0; s < 16; ++s) qreg[s] = qs[h * 33 + off + s];

        float l = 0.f;
        float hacc[16];
        #pragma unroll
        for (int s = 0; s < 16; ++s) hacc[s] = 0.f;
        for (int g = 0; g < Hx; g += 2) {
            float sc0 = 0.f, sc1 = 0.f;
            #pragma unroll
            for (int s = 0; s < 16; ++s) {
                sc0 = fmaf(qreg[s], ks[g * 33 + off + s], sc0);
                sc1 = fmaf(qreg[s], ks[(g + 1) * 33 + off + s], sc1);
            }
            sc0 += __shfl_xor_sync(0xffffffffu, sc0, 1);
            sc1 += __shfl_xor_sync(0xffffffffu, sc1, 1);
            float p0 = __expf(sc0);
            float p1 = __expf(sc1);
            l += p0 + p1;
            #pragma unroll
            for (int s = 0; s < 16; ++s) {
                hacc[s] = fmaf(p0, vs[g * 33 + off + s], hacc[s]);
                hacc[s] = fmaf(p1, vs[(g + 1) * 33 + off + s], hacc[s]);
            }
        }
        float inv = 1.0f / l;
        #pragma unroll
        for (int s = 0; s < 16; ++s)
            g_att[(size_t)xid * HS + h * Sx + off + s] = hacc[s] * inv;
    }
}

// ---------------- fused head-mean+relu + gate partial GEMMs ----------------
__global__ void k_gates2(const float* __restrict__ Wi, const float* __restrict__ Wg,
                         const float* __restrict__ Wo) {
    int gate = blockIdx.x >> 7;          // 0..2
    int ksl  = blockIdx.x & 127;         // 0..127
    int k0 = ksl * 32;
    int j = threadIdx.x;
    __shared__ float a_sm[Bx * 32];
    for (int idx = threadIdx.x; idx < Bx * 32; idx += 128) {
        int b = idx >> 5, rr = idx & 31;
        float v = g_att[(size_t)(b * 4 + 0) * HS + k0 + rr]
                + g_att[(size_t)(b * 4 + 1) * HS + k0 + rr]
                + g_att[(size_t)(b * 4 + 2) * HS + k0 + rr]
                + g_att[(size_t)(b * 4 + 3) * HS + k0 + rr];
        a_sm[idx] = fmaxf(0.25f * v, 0.f);
    }
    __syncthreads();
    const float* W = (gate == 0) ? Wi : (gate == 1) ? Wg : Wo;
    float acc[16];
    #pragma unroll
    for (int b = 0; b < 16; ++b) acc[b] = 0.f;
    #pragma unroll 8
    for (int rr = 0; rr < 32; ++rr) {
        float w = W[(size_t)(k0 + rr) * 128 + j];
        #pragma unroll
        for (int b = 0; b < 16; ++b)
            acc[b] = fmaf(a_sm[b * 32 + rr], w, acc[b]);
    }
    #pragma unroll
    for (int b = 0; b < 16; ++b)
        g_gpart[(size_t)blockIdx.x * (Bx * Hx) + b * 128 + j] = acc[b];
}

// ---------------- gate nonlins + h + fc + reparam z + KL partial (+ optional dec12) ----------------
__global__ void k_finz(const float* __restrict__ w_fc, const float* __restrict__ b_fc,
                       float* __restrict__ z_out, unsigned int key1,
                       const float* __restrict__ w1, const float* __restrict__ b1,
                       const float* __restrict__ w2, const float* __restrict__ b2,
                       double* __restrict__ klpart, int do_decode) {
    int b = blockIdx.x;
    int j = threadIdx.x;
    __shared__ float hv[128];
    __shared__ double dred[128];
    float si = 0.f, sg = 0.f, so = 0.f;
    #pragma unroll 16
    for (int p = 0; p < GSLICES; ++p) {
        si += g_gpart[(size_t)(0 * GSLICES + p) * 2048 + b * 128 + j];
        sg += g_gpart[(size_t)(1 * GSLICES + p) * 2048 + b * 128 + j];
        so += g_gpart[(size_t)(2 * GSLICES + p) * 2048 + b * 128 + j];
    }
    float iv = 1.f / (1.f + expf(-si));
    float gv = tanhf(sg);
    float ov = 1.f / (1.f + expf(-so));
    hv[j] = ov * tanhf(iv * gv);         // c = i*g since c0 = 0
    __syncthreads();
    float mu = b_fc[j], lv = b_fc[128 + j];
    #pragma unroll 8
    for (int k = 0; k < 128; ++k) {
        float hh = hv[k];
        mu = fmaf(hh, w_fc[k * 256 + j], mu);
        lv = fmaf(hh, w_fc[k * 256 + 128 + j], lv);
    }
    {
        double md = (double)mu, ld = (double)lv;
        dred[j] = md * md + (expm1(ld) - ld);
    }
    float eps = tf_normal(key1, (unsigned)(b * 128 + j));
    float z = mu + eps * expf(0.5f * lv);
    z_out[b * 128 + j] = z;
    __syncthreads();
    for (int k = 64; k > 0; k >>= 1) {
        if (j < k) dred[j] += dred[j + k];
        __syncthreads();
    }
    if (j == 0) klpart[b] = dred[0];

    if (do_decode) {
        __shared__ float zsm[128], h1[128];
        zsm[j] = z;
        __syncthreads();
        float acc = b1[j];
        #pragma unroll 8
        for (int k = 0; k < 128; ++k) acc = fmaf(zsm[k], w1[k * 128 + j], acc);
        h1[j] = fmaxf(acc, 0.f);
        __syncthreads();
        acc = b2[j];
        #pragma unroll 8
        for (int k = 0; k < 128; ++k) acc = fmaf(h1[k], w2[k * 128 + j], acc);
        g_h2[b * 128 + j] = fmaxf(acc, 0.f);
    }
}

// ---------------- both KL finals ----------------
__global__ void k_klboth(float* __restrict__ kl1, float* __restrict__ kl2) {
    int t = threadIdx.x;
    if (t == 0) {
        double s = 0.0;
        #pragma unroll
        for (int b = 0; b < Bx; ++b) s += g_klpart1[b];
        kl1[0] = (float)(0.5 * s / 2048.0);
    } else if (t == 1) {
        double s = 0.0;
        #pragma unroll
        for (int b = 0; b < Bx; ++b) s += g_klpart2[b];
        kl2[0] = (float)(0.5 * s / 2048.0);
    }
}

// ---------------- t63 slice stage A: partial GEMM over 8-k chunks ----------------
__global__ void __launch_bounds__(128)
k_d63a(const float* __restrict__ w3) {
    int colblk = blockIdx.x >> 4;        // 0..7
    int kc     = blockIdx.x & 15;        // 0..15
    int k0 = kc * 8;
    int tid = threadIdx.x;
    __shared__ float h2s[Bx][8];
    {
        int b = tid >> 3, kk = tid & 7;
        h2s[b][kk] = g_h2[b * 128 + k0 + kk];
    }
    __syncthreads();
    int cj = colblk * 128 + tid;         // 0..1023
    int j4 = J4_T63 + cj;
    const float4* w4 = (const float4*)w3;
    float4 acc[16];
    #pragma unroll
    for (int b = 0; b < 16; ++b) acc[b] = make_float4(0.f, 0.f, 0.f, 0.f);
    #pragma unroll
    for (int kk = 0; kk < 8; ++kk) {
        float4 w = w4[(size_t)(k0 + kk) * J4_ALL + j4];
        #pragma unroll
        for (int b = 0; b < 16; ++b) {
            float hb = h2s[b][kk];
            acc[b].x = fmaf(hb, w.x, acc[b].x);
            acc[b].y = fmaf(hb, w.y, acc[b].y);
            acc[b].z = fmaf(hb, w.z, acc[b].z);
            acc[b].w = fmaf(hb, w.w, acc[b].w);
        }
    }
    #pragma unroll
    for (int b = 0; b < 16; ++b)
        g_p63[((size_t)kc * Bx + b) * T63_J4N + cj] = acc[b];
}

// ---------------- t63 slice stage B: reduce 16 partials + bias -> xhat ----------------
__global__ void __launch_bounds__(128)
k_d63b(const float* __restrict__ b3, float* __restrict__ xhat) {
    int idx = blockIdx.x * 128 + threadIdx.x;   // 0..16383
    int b  = idx >> 10;
    int cj = idx & 1023;
    int j4 = J4_T63 + cj;
    float4 bias = ((const float4*)b3)[j4];
    float4 s = bias;
    #pragma unroll
    for (int kc = 0; kc < T63_KC; ++kc) {
        float4 p = g_p63[((size_t)kc * Bx + b) * T63_J4N + cj];
        s.x += p.x; s.y += p.y; s.z += p.z; s.w += p.w;
    }
    ((float4*)xhat)[(size_t)b * J4_ALL + j4] = s;
}

// ---------------- decoder big GEMM (rest columns), b split into quarters ----------------
__global__ void __launch_bounds__(128)
k_dec3(const float* __restrict__ w3, const float* __restrict__ b3,
       float* __restrict__ xhat) {
    int bq     = blockIdx.x & 3;         // 0..3: b in [bq*4, bq*4+4)
    int colblk = blockIdx.x >> 2;        // 0..503
    __shared__ float hsm[4 * 128];
    for (int i = threadIdx.x; i < 4 * 128; i += 128)
        hsm[i] = g_h2[bq * 4 * 128 + i];
    __syncthreads();
    int j4 = colblk * 128 + threadIdx.x;
    const float4* w4 = (const float4*)w3;
    float4 bias = ((const float4*)b3)[j4];
    float4 acc[4];
    #pragma unroll
    for (int b = 0; b < 4; ++b) acc[b] = bias;
    #pragma unroll 8
    for (int k = 0; k < 128; ++k) {
        float4 w = w4[(size_t)k * J4_ALL + j4];
        #pragma unroll
        for (int b = 0; b < 4; ++b) {
            float hb = hsm[b * 128 + k];
            acc[b].x = fmaf(hb, w.x, acc[b].x);
            acc[b].y = fmaf(hb, w.y, acc[b].y);
            acc[b].z = fmaf(hb, w.z, acc[b].z);
            acc[b].w = fmaf(hb, w.w, acc[b].w);
        }
    }
    float4* out4 = (float4*)xhat;
    #pragma unroll
    for (int b = 0; b < 4; ++b)
        out4[(size_t)(bq * 4 + b) * J4_ALL + j4] = acc[b];
}

// ---------------- launch ----------------
extern "C" void kernel_launch(void* const* d_in, const int* in_sizes, int n_in,
                              void* d_out, int out_size) {
    const float* x     = (const float*)d_in[0];
    const float* w_enc = (const float*)d_in[1];
    const float* b_enc = (const float*)d_in[2];
    const float* wq = (const float*)d_in[3];
    const float* bq = (const float*)d_in[4];
    const float* wk = (const float*)d_in[5];
    const float* bk = (const float*)d_in[6];
    const float* wv = (const float*)d_in[7];
    const float* bv = (const float*)d_in[8];
    const float* W_ii = (const float*)d_in[9];
    const float* W_ig = (const float*)d_in[13];
    const float* W_io = (const float*)d_in[15];
    const float* w_fc = (const float*)d_in[17];
    const float* b_fc = (const float*)d_in[18];
    const float* w_d1 = (const float*)d_in[19];
    const float* b_d1 = (const float*)d_in[20];
    const float* w_d2 = (const float*)d_in[21];
    const float* b_d2 = (const float*)d_in[22];
    const float* w_d3 = (const float*)d_in[23];
    const float* b_d3 = (const float*)d_in[24];

    float* out  = (float*)d_out;
    float* xhat = out;
    float* z1   = out + OFF_Z1;
    float* z2   = out + OFF_Z2;
    float* kl1  = out + OFF_KL1;
    float* kl2  = out + OFF_KL2;

    // One-time host resources. s_aux gets LOWEST priority so the background
    // decoder yields block-dispatch slots to the critical chain.
    static cudaStream_t s_aux = nullptr;
    static cudaEvent_t ev_fork = nullptr, ev_join = nullptr;
    static bool smem_set = false;
    if (s_aux == nullptr) {
        int prio_lo = 0, prio_hi = 0;
        cudaDeviceGetStreamPriorityRange(&prio_lo, &prio_hi);  // prio_lo = least urgent
        cudaStreamCreateWithPriority(&s_aux, cudaStreamNonBlocking, prio_lo);
        cudaEventCreateWithFlags(&ev_fork, cudaEventDisableTiming);
        cudaEventCreateWithFlags(&ev_join, cudaEventDisableTiming);
    }
    if (!smem_set) {
        cudaFuncSetAttribute(k_enc, cudaFuncAttributeMaxDynamicSharedMemorySize, ENC_SMEM);
        smem_set = true;
    }

    double* klp1;  cudaGetSymbolAddress((void**)&klp1, g_klpart1);
    double* klp2;  cudaGetSymbolAddress((void**)&klp2, g_klpart2);

    // ---- encode 1 (only t = T-1 matters) ----
    k_enc<<<64, 384, ENC_SMEM>>>(x + T63OFF, w_enc, b_enc, wq, bq, wk, bk, wv, bv);
    k_gates2<<<384, 128>>>(W_ii, W_ig, W_io);
    k_finz<<<16, 128>>>(w_fc, b_fc, z1, 1u, w_d1, b_d1, w_d2, b_d2, klp1, 1);
    cudaEventRecord(ev_fork, 0);          // g_h2 ready

    // ---- t63 slice FIRST on the default-priority stream (critical path) ----
    k_d63a<<<128, 128>>>(w_d3);
    k_d63b<<<128, 128>>>(b_d3, xhat);

    // ---- background: rest of decoder on the LOW-priority stream ----
    cudaStreamWaitEvent(s_aux, ev_fork, 0);
    k_dec3<<<2016, 128, 0, s_aux>>>(w_d3, b_d3, xhat);
    cudaEventRecord(ev_join, s_aux);

    // ---- encode 2 on x_hat[t=63] (hidden under dec3_rest) ----
    k_enc<<<64, 384, ENC_SMEM>>>(xhat + T63OFF, w_enc, b_enc, wq, bq, wk, bk, wv, bv);
    k_gates2<<<384, 128>>>(W_ii, W_ig, W_io);
    k_finz<<<16, 128>>>(w_fc, b_fc, z2, 2u, w_d1, b_d1, w_d2, b_d2, klp2, 0);
    k_klboth<<<1, 32>>>(kl1, kl2);

    // join
    cudaStreamWaitEvent(0, ev_join, 0);
}